// round 12
// baseline (speedup 1.0000x reference)
#include <cuda_runtime.h>
#include <cstdint>

#define BATCH 128
#define NNODE 2048
#define ND 128      // NODE_DIM
#define QD 256      // QUERY_DIM
#define OD 256      // OUT_DIM
#define SLICES 2
#define SLICE_NODES (NNODE/SLICES)          // 1024
#define K1_WARPS 8
#define K1_THREADS 256
#define NODES_PER_WARP (SLICE_NODES/K1_WARPS)  // 128
#define BT 8                                 // nodes per register batch
#define NB (NODES_PER_WARP/BT)               // 16 batches
#define PSTRIDE 272                          // floats per partial record (16B-friendly)

__device__ __align__(16) float g_q1t[BATCH*ND];
__device__ __align__(16) float g_q2t[BATCH*ND];
__device__ __align__(16) float g_part[BATCH*SLICES*PSTRIDE];

// ---------------- kernel 0: per-batch query precompute ----------------
// Phase 1 (rewritten): warp-cooperative dots — lanes read contiguous 512B row
// segments (coalesced), 4 outputs in flight per step for MLP.
__global__ __launch_bounds__(256)
void k0_qprep(const float* __restrict__ fp_vec,
              const float* __restrict__ Wq1,
              const float* __restrict__ Wq2,
              const float* __restrict__ Wk)
{
    __shared__ __align__(16) float q1s[ND], q2s[ND];
    const int t = threadIdx.x, b = blockIdx.x;
    const int w = t >> 5, l = t & 31;

    // ---- phase 1: q1s[e] = fp[b]·Wq1[e,:], q2s[e] = fp[b]·Wq2[e,:] ----
    {
        const float4* fp4 = (const float4*)(fp_vec + b*QD);
        const float4 fa = fp4[l], fb = fp4[l + 32];   // lane's two fp segments

        // warp w owns outputs o = w*32 .. w*32+31 (o<128 -> q1s[o], else q2s[o-128])
        #pragma unroll
        for (int k = 0; k < 32; k += 4) {
            float p[4];
            #pragma unroll
            for (int j = 0; j < 4; j++) {
                const int o = w*32 + k + j;
                const float* rowp = (o < ND) ? (Wq1 + o*QD) : (Wq2 + (o-ND)*QD);
                const float4* r4 = (const float4*)rowp;
                float4 ra = r4[l], rb = r4[l + 32];   // coalesced 512B each
                p[j] = fa.x*ra.x + fa.y*ra.y + fa.z*ra.z + fa.w*ra.w
                     + fb.x*rb.x + fb.y*rb.y + fb.z*rb.z + fb.w*rb.w;
            }
            #pragma unroll
            for (int o2 = 16; o2 > 0; o2 >>= 1) {
                p[0] += __shfl_xor_sync(0xffffffffu, p[0], o2);
                p[1] += __shfl_xor_sync(0xffffffffu, p[1], o2);
                p[2] += __shfl_xor_sync(0xffffffffu, p[2], o2);
                p[3] += __shfl_xor_sync(0xffffffffu, p[3], o2);
            }
            if (l < 4) {
                const int o = w*32 + k + l;
                float v = (l==0) ? p[0] : (l==1) ? p[1] : (l==2) ? p[2] : p[3];
                if (o < ND) q1s[o] = v; else q2s[o-ND] = v;
            }
        }
    }
    __syncthreads();

    // ---- phase 2: q{1,2}t[d] = (sum_e q{1,2}s[e]*Wk[e,d]) * inv_scale ----
    {
        const int d = t & (ND-1);
        const float* qs = (t < ND) ? q1s : q2s;
        float s = 0.f;
        #pragma unroll 8
        for (int e = 0; e < ND; e++) s += qs[e] * Wk[e*ND + d];   // coalesced over d
        s *= 0.08838834764831845f;   // 1/sqrt(128)
        if (t < ND) g_q1t[b*ND + d] = s; else g_q2t[b*ND + d] = s;
    }
}

// ---------------- kernel 1: streaming attention partials ----------------
#define COMPUTE(X, ii) { \
    float p1[BT], p2[BT]; \
    _Pragma("unroll") for (int j = 0; j < BT; j++) { \
        p1[j] = X[j].x*q1r.x + X[j].y*q1r.y + X[j].z*q1r.z + X[j].w*q1r.w; \
        p2[j] = X[j].x*q2r.x + X[j].y*q2r.y + X[j].z*q2r.z + X[j].w*q2r.w; } \
    _Pragma("unroll") for (int o = 16; o > 0; o >>= 1) { \
        _Pragma("unroll") for (int j = 0; j < BT; j++) { \
            p1[j] += __shfl_xor_sync(0xffffffffu, p1[j], o); \
            p2[j] += __shfl_xor_sync(0xffffffffu, p2[j], o); } } \
    _Pragma("unroll") for (int j = 0; j < BT; j++) { \
        float pd = pads[pbase + (ii)*BT + j]; \
        float e1 = __expf(p1[j] + pd); \
        float e2 = __expf(p2[j] + pd); \
        L1 += e1; L2 += e2; \
        c1.x += e1*X[j].x; c1.y += e1*X[j].y; c1.z += e1*X[j].z; c1.w += e1*X[j].w; \
        c2.x += e2*X[j].x; c2.y += e2*X[j].y; c2.z += e2*X[j].z; c2.w += e2*X[j].w; } }

__global__ __launch_bounds__(K1_THREADS, 2)
void k1_stream(const float* __restrict__ node_mat,
               const void*  __restrict__ mask)
{
    __shared__ float pads[SLICE_NODES];                               // 4 KB
    __shared__ __align__(16) float wacc1[K1_WARPS*ND], wacc2[K1_WARPS*ND];  // 8 KB
    __shared__ float wl1[K1_WARPS], wl2[K1_WARPS];
    __shared__ int smode;

    const int t = threadIdx.x;
    const int bid = blockIdx.x;
    const int b = bid >> 1, q = bid & 1;
    const int w = t >> 5, l = t & 31;

    if (t == 0) smode = 0;
    __syncthreads();
    // mask dtype sniff: words [b*512, b*512+512) — in-bounds under u8 hypothesis (256KB)
    {
        const unsigned* mw = (const unsigned*)mask;
        #pragma unroll
        for (int r = 0; r < 2; r++) {
            unsigned v = mw[b*512 + t + r*256];
            int f = 0;
            if (v == 0x3F800000u)        f = 2;   // fp32 one
            else if (v != 0u && v != 1u) f = 1;   // byte-packed bool signature
            if (f) atomicOr(&smode, f);
        }
    }
    __syncthreads();
    {
        const int mode = smode;
        const size_t off = (size_t)b*NNODE + q*SLICE_NODES;
        const int*           mi  = (const int*)mask           + off;
        const unsigned char* mu8 = (const unsigned char*)mask + off;
        const float*         mf  = (const float*)mask         + off;
        #pragma unroll
        for (int r = 0; r < SLICE_NODES/K1_THREADS; r++) {
            int n = t + r*K1_THREADS;
            bool valid;
            if (mode & 1)      valid = mu8[n] != 0;
            else if (mode & 2) valid = mf[n]  != 0.f;
            else               valid = mi[n]  != 0;
            pads[n] = valid ? 0.f : -1e9f;
        }
    }
    const float4 q1r = ((const float4*)(g_q1t + b*ND))[l];   // lane owns dims [4l,4l+4)
    const float4 q2r = ((const float4*)(g_q2t + b*ND))[l];
    __syncthreads();

    // this warp's contiguous 128-node region
    const float4* p = (const float4*)node_mat
        + ((size_t)b*NNODE + q*SLICE_NODES + w*NODES_PER_WARP) * (ND/4) + l;
    const int pbase = w*NODES_PER_WARP;

    float4 c1 = make_float4(0.f,0.f,0.f,0.f), c2 = c1;
    float L1 = 0.f, L2 = 0.f;

    float4 A[BT], Bf[BT];
    #pragma unroll
    for (int j = 0; j < BT; j++) A[j] = p[j*32];     // batch 0

    for (int i = 0; i < NB; i += 2) {
        #pragma unroll
        for (int j = 0; j < BT; j++) Bf[j] = p[((i+1)*BT + j)*32];   // prefetch batch i+1
        COMPUTE(A, i)
        if (i + 2 < NB) {
            #pragma unroll
            for (int j = 0; j < BT; j++) A[j] = p[((i+2)*BT + j)*32]; // prefetch batch i+2
        }
        COMPUTE(Bf, i+1)
    }

    // publish per-warp partials
    ((float4*)(wacc1 + w*ND))[l] = c1;
    ((float4*)(wacc2 + w*ND))[l] = c2;
    if (l == 0) { wl1[w] = L1; wl2[w] = L2; }
    __syncthreads();

    if (t < ND) {
        float z1 = 0.f, z2 = 0.f;
        #pragma unroll
        for (int k = 0; k < K1_WARPS; k++) { z1 += wacc1[k*ND + t]; z2 += wacc2[k*ND + t]; }
        float* P = g_part + (size_t)bid*PSTRIDE;
        P[t] = z1; P[ND + t] = z2;
    }
    if (t == 0) {
        float tL1 = 0.f, tL2 = 0.f;
        #pragma unroll
        for (int k = 0; k < K1_WARPS; k++) { tL1 += wl1[k]; tL2 += wl2[k]; }
        float* P = g_part + (size_t)bid*PSTRIDE;
        P[2*ND] = tL1; P[2*ND+1] = tL2;
    }
}

// ---------------- kernel 2: merge + Wv + LayerNorm ----------------
__global__ __launch_bounds__(256)
void k2_epi(const float* __restrict__ Wv,
            const float* __restrict__ lambda_logit,
            const float* __restrict__ gamma,
            const float* __restrict__ beta,
            float* __restrict__ out)
{
    __shared__ __align__(16) float ztd[ND];
    __shared__ float red[8];
    const int t = threadIdx.x, b = blockIdx.x;
    const int w = t >> 5, l = t & 31;

    const float* P0 = g_part + (size_t)(b*2)  *PSTRIDE;
    const float* P1 = P0 + PSTRIDE;
    if (t < ND) {
        float z1 = P0[t]      + P1[t];
        float z2 = P0[ND+t]   + P1[ND+t];
        float L1 = P0[2*ND]   + P1[2*ND];
        float L2 = P0[2*ND+1] + P1[2*ND+1];
        float lam = 0.8f + 0.2f / (1.f + __expf(-lambda_logit[0]));
        ztd[t] = z1/L1 - lam*(z2/L2);
    }
    __syncthreads();

    float zv = 0.f;
    {
        const float4* wr = (const float4*)(Wv + t*ND);
        const float4* z4 = (const float4*)ztd;
        #pragma unroll 8
        for (int d4 = 0; d4 < ND/4; d4++) {
            float4 a = z4[d4], ww = wr[d4];
            zv += a.x*ww.x + a.y*ww.y + a.z*ww.z + a.w*ww.w;
        }
    }
    // LayerNorm over OD=256 (all 256 threads hold one element)
    float s = zv;
    #pragma unroll
    for (int o = 16; o > 0; o >>= 1) s += __shfl_xor_sync(0xffffffffu, s, o);
    if (l == 0) red[w] = s;
    __syncthreads();
    float tot = 0.f;
    #pragma unroll
    for (int k = 0; k < 8; k++) tot += red[k];
    float mu = tot / OD;

    float dv = zv - mu;
    float sq = dv*dv;
    __syncthreads();   // red reuse
    #pragma unroll
    for (int o = 16; o > 0; o >>= 1) sq += __shfl_xor_sync(0xffffffffu, sq, o);
    if (l == 0) red[w] = sq;
    __syncthreads();
    float tot2 = 0.f;
    #pragma unroll
    for (int k = 0; k < 8; k++) tot2 += red[k];
    float inv = rsqrtf(tot2 / OD + 1e-5f);

    out[b*OD + t] = dv*inv*gamma[t] + beta[t];
}

extern "C" void kernel_launch(void* const* d_in, const int* in_sizes, int n_in,
                              void* d_out, int out_size) {
    const float* fp_vec   = (const float*)d_in[0];
    const float* node_mat = (const float*)d_in[1];
    const void*  mask     = d_in[2];
    const float* Wq1      = (const float*)d_in[3];
    const float* Wq2      = (const float*)d_in[4];
    const float* Wk       = (const float*)d_in[5];
    const float* Wv       = (const float*)d_in[6];
    const float* lambda_l = (const float*)d_in[7];
    const float* gamma    = (const float*)d_in[8];
    const float* beta     = (const float*)d_in[9];

    k0_qprep<<<BATCH, 256>>>(fp_vec, Wq1, Wq2, Wk);
    k1_stream<<<BATCH*SLICES, K1_THREADS>>>(node_mat, mask);
    k2_epi<<<BATCH, 256>>>(Wv, lambda_l, gamma, beta, (float*)d_out);
}

// round 13
// speedup vs baseline: 1.2011x; 1.2011x over previous
#include <cuda_runtime.h>
#include <cstdint>

#define BATCH 128
#define NNODE 2048
#define ND 128      // NODE_DIM
#define QD 256      // QUERY_DIM
#define OD 256      // OUT_DIM
#define SLICES 2
#define SLICE_NODES (NNODE/SLICES)          // 1024
#define K1_WARPS 8
#define K1_THREADS 256
#define NODES_PER_WARP (SLICE_NODES/K1_WARPS)  // 128
#define BT 8                                 // nodes per register batch
#define NB (NODES_PER_WARP/BT)               // 16 batches
#define PSTRIDE 272                          // floats per partial record (16B-friendly)

__device__ __align__(16) float g_q1t[BATCH*ND];
__device__ __align__(16) float g_q2t[BATCH*ND];
__device__ __align__(16) float g_part[BATCH*SLICES*PSTRIDE];

// ---------------- kernel 0: per-batch query precompute ----------------
// Grid = 256 CTAs: (batch, branch). Each CTA: 128 phase-1 outputs via
// warp-cooperative dots (16/warp, 4-way interleaved butterflies), then
// phase-2 split-K (2 threads per output) — short latency chains everywhere.
__global__ __launch_bounds__(256)
void k0_qprep(const float* __restrict__ fp_vec,
              const float* __restrict__ Wq1,
              const float* __restrict__ Wq2,
              const float* __restrict__ Wk)
{
    __shared__ __align__(16) float qs[ND];
    __shared__ __align__(16) float part[2*ND];
    const int t = threadIdx.x;
    const int b  = blockIdx.x >> 1;
    const int br = blockIdx.x & 1;
    const int w = t >> 5, l = t & 31;
    const float* Wq = br ? Wq2 : Wq1;

    // ---- phase 1: qs[o] = fp[b] · Wq[o,:]   (16 outputs per warp) ----
    {
        const float4* fp4 = (const float4*)(fp_vec + b*QD);
        const float4 fa = fp4[l], fb = fp4[l + 32];
        #pragma unroll
        for (int k = 0; k < 16; k += 4) {
            float p[4];
            #pragma unroll
            for (int j = 0; j < 4; j++) {
                const float4* r4 = (const float4*)(Wq + (w*16 + k + j)*QD);
                float4 ra = r4[l], rb = r4[l + 32];   // coalesced 512B each
                p[j] = fa.x*ra.x + fa.y*ra.y + fa.z*ra.z + fa.w*ra.w
                     + fb.x*rb.x + fb.y*rb.y + fb.z*rb.z + fb.w*rb.w;
            }
            #pragma unroll
            for (int o2 = 16; o2 > 0; o2 >>= 1) {
                p[0] += __shfl_xor_sync(0xffffffffu, p[0], o2);
                p[1] += __shfl_xor_sync(0xffffffffu, p[1], o2);
                p[2] += __shfl_xor_sync(0xffffffffu, p[2], o2);
                p[3] += __shfl_xor_sync(0xffffffffu, p[3], o2);
            }
            if (l < 4) {
                float v = (l==0) ? p[0] : (l==1) ? p[1] : (l==2) ? p[2] : p[3];
                qs[w*16 + k + l] = v;
            }
        }
    }
    __syncthreads();

    // ---- phase 2 (split-K): qt[d] = inv_scale * sum_e qs[e]*Wk[e,d] ----
    {
        const int d    = t & (ND-1);
        const int half = t >> 7;             // 0: e in [0,64), 1: e in [64,128)
        const int e0   = half * 64;
        float s0 = 0.f, s1 = 0.f, s2 = 0.f, s3 = 0.f;
        #pragma unroll
        for (int e = 0; e < 64; e += 4) {    // 4 accumulators, coalesced over d
            s0 += qs[e0+e+0] * Wk[(e0+e+0)*ND + d];
            s1 += qs[e0+e+1] * Wk[(e0+e+1)*ND + d];
            s2 += qs[e0+e+2] * Wk[(e0+e+2)*ND + d];
            s3 += qs[e0+e+3] * Wk[(e0+e+3)*ND + d];
        }
        part[half*ND + d] = (s0+s1) + (s2+s3);
    }
    __syncthreads();
    if (t < ND) {
        float s = (part[t] + part[ND + t]) * 0.08838834764831845f;  // 1/sqrt(128)
        if (br == 0) g_q1t[b*ND + t] = s; else g_q2t[b*ND + t] = s;
    }
}

// ---------------- kernel 1: streaming attention partials ----------------
#define COMPUTE(X, ii) { \
    float p1[BT], p2[BT]; \
    _Pragma("unroll") for (int j = 0; j < BT; j++) { \
        p1[j] = X[j].x*q1r.x + X[j].y*q1r.y + X[j].z*q1r.z + X[j].w*q1r.w; \
        p2[j] = X[j].x*q2r.x + X[j].y*q2r.y + X[j].z*q2r.z + X[j].w*q2r.w; } \
    _Pragma("unroll") for (int o = 16; o > 0; o >>= 1) { \
        _Pragma("unroll") for (int j = 0; j < BT; j++) { \
            p1[j] += __shfl_xor_sync(0xffffffffu, p1[j], o); \
            p2[j] += __shfl_xor_sync(0xffffffffu, p2[j], o); } } \
    _Pragma("unroll") for (int j = 0; j < BT; j++) { \
        float pd = pads[pbase + (ii)*BT + j]; \
        float e1 = __expf(p1[j] + pd); \
        float e2 = __expf(p2[j] + pd); \
        L1 += e1; L2 += e2; \
        c1.x += e1*X[j].x; c1.y += e1*X[j].y; c1.z += e1*X[j].z; c1.w += e1*X[j].w; \
        c2.x += e2*X[j].x; c2.y += e2*X[j].y; c2.z += e2*X[j].z; c2.w += e2*X[j].w; } }

__global__ __launch_bounds__(K1_THREADS, 2)
void k1_stream(const float* __restrict__ node_mat,
               const void*  __restrict__ mask)
{
    __shared__ float pads[SLICE_NODES];                               // 4 KB
    __shared__ __align__(16) float wacc1[K1_WARPS*ND], wacc2[K1_WARPS*ND];  // 8 KB
    __shared__ float wl1[K1_WARPS], wl2[K1_WARPS];
    __shared__ int smode;

    const int t = threadIdx.x;
    const int bid = blockIdx.x;
    const int b = bid >> 1, q = bid & 1;
    const int w = t >> 5, l = t & 31;

    if (t == 0) smode = 0;
    __syncthreads();
    // mask dtype sniff: words [b*512, b*512+512) — in-bounds under u8 hypothesis (256KB)
    {
        const unsigned* mw = (const unsigned*)mask;
        #pragma unroll
        for (int r = 0; r < 2; r++) {
            unsigned v = mw[b*512 + t + r*256];
            int f = 0;
            if (v == 0x3F800000u)        f = 2;   // fp32 one
            else if (v != 0u && v != 1u) f = 1;   // byte-packed bool signature
            if (f) atomicOr(&smode, f);
        }
    }
    __syncthreads();
    {
        const int mode = smode;
        const size_t off = (size_t)b*NNODE + q*SLICE_NODES;
        const int*           mi  = (const int*)mask           + off;
        const unsigned char* mu8 = (const unsigned char*)mask + off;
        const float*         mf  = (const float*)mask         + off;
        #pragma unroll
        for (int r = 0; r < SLICE_NODES/K1_THREADS; r++) {
            int n = t + r*K1_THREADS;
            bool valid;
            if (mode & 1)      valid = mu8[n] != 0;
            else if (mode & 2) valid = mf[n]  != 0.f;
            else               valid = mi[n]  != 0;
            pads[n] = valid ? 0.f : -1e9f;
        }
    }
    const float4 q1r = ((const float4*)(g_q1t + b*ND))[l];   // lane owns dims [4l,4l+4)
    const float4 q2r = ((const float4*)(g_q2t + b*ND))[l];
    __syncthreads();

    // this warp's contiguous 128-node region
    const float4* p = (const float4*)node_mat
        + ((size_t)b*NNODE + q*SLICE_NODES + w*NODES_PER_WARP) * (ND/4) + l;
    const int pbase = w*NODES_PER_WARP;

    float4 c1 = make_float4(0.f,0.f,0.f,0.f), c2 = c1;
    float L1 = 0.f, L2 = 0.f;

    float4 A[BT], Bf[BT];
    #pragma unroll
    for (int j = 0; j < BT; j++) A[j] = p[j*32];     // batch 0

    for (int i = 0; i < NB; i += 2) {
        #pragma unroll
        for (int j = 0; j < BT; j++) Bf[j] = p[((i+1)*BT + j)*32];   // prefetch batch i+1
        COMPUTE(A, i)
        if (i + 2 < NB) {
            #pragma unroll
            for (int j = 0; j < BT; j++) A[j] = p[((i+2)*BT + j)*32]; // prefetch batch i+2
        }
        COMPUTE(Bf, i+1)
    }

    // publish per-warp partials
    ((float4*)(wacc1 + w*ND))[l] = c1;
    ((float4*)(wacc2 + w*ND))[l] = c2;
    if (l == 0) { wl1[w] = L1; wl2[w] = L2; }
    __syncthreads();

    if (t < ND) {
        float z1 = 0.f, z2 = 0.f;
        #pragma unroll
        for (int k = 0; k < K1_WARPS; k++) { z1 += wacc1[k*ND + t]; z2 += wacc2[k*ND + t]; }
        float* P = g_part + (size_t)bid*PSTRIDE;
        P[t] = z1; P[ND + t] = z2;
    }
    if (t == 0) {
        float tL1 = 0.f, tL2 = 0.f;
        #pragma unroll
        for (int k = 0; k < K1_WARPS; k++) { tL1 += wl1[k]; tL2 += wl2[k]; }
        float* P = g_part + (size_t)bid*PSTRIDE;
        P[2*ND] = tL1; P[2*ND+1] = tL2;
    }
}

// ---------------- kernel 2: merge + Wv + LayerNorm ----------------
__global__ __launch_bounds__(256)
void k2_epi(const float* __restrict__ Wv,
            const float* __restrict__ lambda_logit,
            const float* __restrict__ gamma,
            const float* __restrict__ beta,
            float* __restrict__ out)
{
    __shared__ __align__(16) float ztd[ND];
    __shared__ float red[8];
    const int t = threadIdx.x, b = blockIdx.x;
    const int w = t >> 5, l = t & 31;

    const float* P0 = g_part + (size_t)(b*2)  *PSTRIDE;
    const float* P1 = P0 + PSTRIDE;
    if (t < ND) {
        float z1 = P0[t]      + P1[t];
        float z2 = P0[ND+t]   + P1[ND+t];
        float L1 = P0[2*ND]   + P1[2*ND];
        float L2 = P0[2*ND+1] + P1[2*ND+1];
        float lam = 0.8f + 0.2f / (1.f + __expf(-lambda_logit[0]));
        ztd[t] = z1/L1 - lam*(z2/L2);
    }
    __syncthreads();

    float zv = 0.f;
    {
        const float4* wr = (const float4*)(Wv + t*ND);
        const float4* z4 = (const float4*)ztd;
        #pragma unroll 8
        for (int d4 = 0; d4 < ND/4; d4++) {
            float4 a = z4[d4], ww = wr[d4];
            zv += a.x*ww.x + a.y*ww.y + a.z*ww.z + a.w*ww.w;
        }
    }
    // LayerNorm over OD=256 (all 256 threads hold one element)
    float s = zv;
    #pragma unroll
    for (int o = 16; o > 0; o >>= 1) s += __shfl_xor_sync(0xffffffffu, s, o);
    if (l == 0) red[w] = s;
    __syncthreads();
    float tot = 0.f;
    #pragma unroll
    for (int k = 0; k < 8; k++) tot += red[k];
    float mu = tot / OD;

    float dv = zv - mu;
    float sq = dv*dv;
    __syncthreads();   // red reuse
    #pragma unroll
    for (int o = 16; o > 0; o >>= 1) sq += __shfl_xor_sync(0xffffffffu, sq, o);
    if (l == 0) red[w] = sq;
    __syncthreads();
    float tot2 = 0.f;
    #pragma unroll
    for (int k = 0; k < 8; k++) tot2 += red[k];
    float inv = rsqrtf(tot2 / OD + 1e-5f);

    out[b*OD + t] = dv*inv*gamma[t] + beta[t];
}

extern "C" void kernel_launch(void* const* d_in, const int* in_sizes, int n_in,
                              void* d_out, int out_size) {
    const float* fp_vec   = (const float*)d_in[0];
    const float* node_mat = (const float*)d_in[1];
    const void*  mask     = d_in[2];
    const float* Wq1      = (const float*)d_in[3];
    const float* Wq2      = (const float*)d_in[4];
    const float* Wk       = (const float*)d_in[5];
    const float* Wv       = (const float*)d_in[6];
    const float* lambda_l = (const float*)d_in[7];
    const float* gamma    = (const float*)d_in[8];
    const float* beta     = (const float*)d_in[9];

    k0_qprep<<<BATCH*2, 256>>>(fp_vec, Wq1, Wq2, Wk);
    k1_stream<<<BATCH*SLICES, K1_THREADS>>>(node_mat, mask);
    k2_epi<<<BATCH, 256>>>(Wv, lambda_l, gamma, beta, (float*)d_out);
}